// round 5
// baseline (speedup 1.0000x reference)
#include <cuda_runtime.h>
#include <cstdint>

#define DIM 16
#define HID 32
#define TPB 256
#define WARPS_PER_CTA (TPB / 32)
#define TILES_PER_WARP 8

// ---------------- low-level helpers ----------------
__device__ __forceinline__ unsigned tf32_rna(float f) {   // init-path only
    unsigned u; asm("cvt.rna.tf32.f32 %0, %1;" : "=r"(u) : "f"(f)); return u;
}
__device__ __forceinline__ unsigned bits(float f) { return __float_as_uint(f); }

__device__ __forceinline__ void mma8(float& d0, float& d1, float& d2, float& d3,
                                     unsigned a0, unsigned a1, unsigned a2, unsigned a3,
                                     unsigned b0, unsigned b1) {
    asm volatile(
        "mma.sync.aligned.m16n8k8.row.col.f32.tf32.tf32.f32 "
        "{%0,%1,%2,%3}, {%4,%5,%6,%7}, {%8,%9}, {%0,%1,%2,%3};"
        : "+f"(d0), "+f"(d1), "+f"(d2), "+f"(d3)
        : "r"(a0), "r"(a1), "r"(a2), "r"(a3), "r"(b0), "r"(b1));
}
__device__ __forceinline__ float fast_tanh(float x) {
    float r; asm("tanh.approx.f32 %0, %1;" : "=f"(r) : "f"(x)); return r;
}

union F2U { float2 f; unsigned long long u; };
__device__ __forceinline__ float2 f2fma(float2 a, float2 b, float2 c) {
    F2U A, B, C, R; A.f = a; B.f = b; C.f = c;
    asm("fma.rn.f32x2 %0, %1, %2, %3;" : "=l"(R.u) : "l"(A.u), "l"(B.u), "l"(C.u));
    return R.f;
}
__device__ __forceinline__ float2 f2mul(float2 a, float2 b) {
    F2U A, B, R; A.f = a; B.f = b;
    asm("mul.rn.f32x2 %0, %1, %2;" : "=l"(R.u) : "l"(A.u), "l"(B.u));
    return R.f;
}
__device__ __forceinline__ float2 f2add(float2 a, float2 b) {
    F2U A, B, R; A.f = a; B.f = b;
    asm("add.rn.f32x2 %0, %1, %2;" : "=l"(R.u) : "l"(A.u), "l"(B.u));
    return R.f;
}

// tanh-form GELU on a packed pair
__device__ __forceinline__ float2 gelu2(float2 x) {
    const float C1 = 0.7978845608028654f;            // sqrt(2/pi)
    const float C2 = 0.7978845608028654f * 0.044715f;
    float2 x2 = f2mul(x, x);
    float2 inner = f2fma(x2, make_float2(C2, C2), make_float2(C1, C1));
    float2 y  = f2mul(x, inner);
    float2 t  = make_float2(fast_tanh(y.x), fast_tanh(y.y));
    float2 phi = f2fma(t, make_float2(0.5f, 0.5f), make_float2(0.5f, 0.5f));
    return f2mul(x, phi);
}

// ---------------- fully register-resident tensor-core kernel ----------------
// mma.m16n8k8 tf32 fragment maps (lane = 4g+c):
//   A: a0=(g,kc) a1=(g+8,kc) a2=(g,kc+4) a3=(g+8,kc+4)   [k-pos kc=c]
//   B: b0=(k=c,n=g) b1=(k=c+4,n=g)
//   C: c0=(g,2c) c1=(g,2c+1) c2=(g+8,2c) c3=(g+8,2c+1)
//
// Axis permutations (all folded into weight/bias indexing):
//  GEMM1 k-axis:  MMA kt, k-pos c -> col 4c+2kt ; k-pos c+4 -> col 4c+2kt+1
//     => A1 fragment IS the raw LDG.128 register layout (lane holds cols 4c..4c+3).
//  GEMM2 k-axis:  k-pos s<4 -> hid 8kt+2s ; s>=4 -> 8kt+2(s-4)+1
//     => GEMM1's C fragment IS GEMM2's A fragment.
//  GEMM2 n-axis:  n-pos nt*8+g -> out dim 4*(g>>1)+2nt+(g&1)
//     => lane's C2 values are out cols 4c..4c+3: residual from own x regs, STG.128 stores.
// TF32 A-operands are raw fp32 bits (HW truncates to bits[31:13]).
__global__ void __launch_bounds__(TPB)
fused_ln_mlp_mma(const float* __restrict__ x,
                 const float* __restrict__ ln_w, const float* __restrict__ ln_b,
                 const float* __restrict__ w1,   const float* __restrict__ b1,
                 const float* __restrict__ w2,   const float* __restrict__ b2,
                 float* __restrict__ out, int ntiles)
{
    const int lane = threadIdx.x & 31;
    const int wrp  = threadIdx.x >> 5;
    const int g = lane >> 2;
    const int c = lane & 3;

    // ---- per-warp weight fragments (registers, rna-converted once) ----
    // GEMM1: B1f[kt][nt][j] = w1[nt*8+g][4c+2kt+j]
    unsigned B1f[2][4][2];
    #pragma unroll
    for (int kt = 0; kt < 2; kt++)
        #pragma unroll
        for (int nt = 0; nt < 4; nt++) {
            B1f[kt][nt][0] = tf32_rna(w1[(nt * 8 + g) * DIM + 4 * c + 2 * kt]);
            B1f[kt][nt][1] = tf32_rna(w1[(nt * 8 + g) * DIM + 4 * c + 2 * kt + 1]);
        }
    // GEMM2: n-pos nt*8+g -> out dim od = 4*(g>>1) + 2*nt + (g&1); k-perm: kt*8+2c(+1)
    unsigned B2f[4][2][2];
    #pragma unroll
    for (int nt = 0; nt < 2; nt++) {
        int od = 4 * (g >> 1) + 2 * nt + (g & 1);
        #pragma unroll
        for (int kt = 0; kt < 4; kt++) {
            B2f[kt][nt][0] = tf32_rna(w2[od * HID + kt * 8 + 2 * c]);
            B2f[kt][nt][1] = tf32_rna(w2[od * HID + kt * 8 + 2 * c + 1]);
        }
    }
    // b1 at C1 columns (hidden dims nt*8+2c, +1) -- unpermuted hidden axis for GEMM1 C
    float b1v[4][2];
    #pragma unroll
    for (int nt = 0; nt < 4; nt++) {
        b1v[nt][0] = b1[nt * 8 + 2 * c];
        b1v[nt][1] = b1[nt * 8 + 2 * c + 1];
    }
    // b2 at this lane's out cols: nt -> cols 4c+2nt, 4c+2nt+1
    float2 b2p[2];
    #pragma unroll
    for (int nt = 0; nt < 2; nt++)
        b2p[nt] = make_float2(b2[4 * c + 2 * nt], b2[4 * c + 2 * nt + 1]);
    // LN affine at this lane's cols 4c..4c+3 (vector loads, 16B-aligned)
    const float4 lnw4 = *reinterpret_cast<const float4*>(ln_w + 4 * c);
    const float4 lnb4 = *reinterpret_cast<const float4*>(ln_b + 4 * c);

    const int gwarp = blockIdx.x * WARPS_PER_CTA + wrp;
    const long t0 = (long)gwarp * TILES_PER_WARP;

    // prefetch first tile: lane 4g+c gets rows g and g+8, cols 4c..4c+3
    float4 pa, pb;
    if (t0 < ntiles) {
        const float4* p = reinterpret_cast<const float4*>(x + (size_t)t0 * 16 * DIM);
        pa = p[lane]; pb = p[lane + 32];
    }

    for (int it = 0; it < TILES_PER_WARP; ++it) {
        const long tile = t0 + it;
        if (tile >= ntiles) break;

        const float4 xa = pa, xb = pb;     // row g / row g+8, cols 4c..4c+3
        if (it + 1 < TILES_PER_WARP && tile + 1 < ntiles) {
            const float4* p = reinterpret_cast<const float4*>(x + (size_t)(tile + 1) * 16 * DIM);
            pa = p[lane]; pb = p[lane + 32];
        }

        // packed (row g, row g+8) views of the 4 held columns
        float2 xp[4] = { make_float2(xa.x, xb.x), make_float2(xa.y, xb.y),
                         make_float2(xa.z, xb.z), make_float2(xa.w, xb.w) };

        // ---- LayerNorm stats (packed) + quad reduction ----
        float2 s = f2add(f2add(xp[0], xp[1]), f2add(xp[2], xp[3]));
        float2 q = f2mul(xp[0], xp[0]);
        q = f2fma(xp[1], xp[1], q);
        q = f2fma(xp[2], xp[2], q);
        q = f2fma(xp[3], xp[3], q);
        s.x += __shfl_xor_sync(0xffffffffu, s.x, 1); s.x += __shfl_xor_sync(0xffffffffu, s.x, 2);
        s.y += __shfl_xor_sync(0xffffffffu, s.y, 1); s.y += __shfl_xor_sync(0xffffffffu, s.y, 2);
        q.x += __shfl_xor_sync(0xffffffffu, q.x, 1); q.x += __shfl_xor_sync(0xffffffffu, q.x, 2);
        q.y += __shfl_xor_sync(0xffffffffu, q.y, 1); q.y += __shfl_xor_sync(0xffffffffu, q.y, 2);
        const float inv = 1.0f / 16.0f;
        float2 mup = f2mul(s, make_float2(inv, inv));
        float2 qi  = f2mul(q, make_float2(inv, inv));
        float rstd0 = rsqrtf(fmaf(-mup.x, mup.x, qi.x) + 1e-5f);
        float rstd1 = rsqrtf(fmaf(-mup.y, mup.y, qi.y) + 1e-5f);
        float2 rstdp = make_float2(rstd0, rstd1);
        float2 nmup  = make_float2(-mup.x * rstd0, -mup.y * rstd1);

        // xn_j = x * (rstd*lnw_j) + (nmu*lnw_j + lnb_j)  for held cols j=0..3
        const float lnw[4] = { lnw4.x, lnw4.y, lnw4.z, lnw4.w };
        const float lnb[4] = { lnb4.x, lnb4.y, lnb4.z, lnb4.w };
        float2 xn[4];
        #pragma unroll
        for (int j = 0; j < 4; j++) {
            float2 wj = make_float2(lnw[j], lnw[j]);
            float2 a = f2mul(rstdp, wj);
            float2 b = f2fma(nmup, wj, make_float2(lnb[j], lnb[j]));
            xn[j] = f2fma(xp[j], a, b);
        }

        // ---- GEMM1 (8 mma), A straight from registers; seeded with b1 ----
        // MMA kt uses held cols {2kt, 2kt+1}: a0/a1 = col 2kt (rows g,g+8), a2/a3 = col 2kt+1
        float C1[4][4];
        #pragma unroll
        for (int nt = 0; nt < 4; nt++) {
            C1[nt][0] = b1v[nt][0]; C1[nt][1] = b1v[nt][1];
            C1[nt][2] = b1v[nt][0]; C1[nt][3] = b1v[nt][1];
            mma8(C1[nt][0], C1[nt][1], C1[nt][2], C1[nt][3],
                 bits(xn[0].x), bits(xn[0].y), bits(xn[1].x), bits(xn[1].y),
                 B1f[0][nt][0], B1f[0][nt][1]);
            mma8(C1[nt][0], C1[nt][1], C1[nt][2], C1[nt][3],
                 bits(xn[2].x), bits(xn[2].y), bits(xn[3].x), bits(xn[3].y),
                 B1f[1][nt][0], B1f[1][nt][1]);
        }

        // ---- GELU; C1 fragment IS the GEMM2 A fragment ----
        float2 ga[4], gb[4];
        #pragma unroll
        for (int kt = 0; kt < 4; kt++) {
            ga[kt] = gelu2(make_float2(C1[kt][0], C1[kt][1]));   // row g:   (a0,a2)
            gb[kt] = gelu2(make_float2(C1[kt][2], C1[kt][3]));   // row g+8: (a1,a3)
        }

        // ---- GEMM2 (8 mma), seeded with b2 + residual from own x registers ----
        // C2[nt] columns = out cols 4c+2nt, 4c+2nt+1  (sigma n-perm)
        float C2[2][4];
        {
            float2 r0a = make_float2(xa.x, xa.y), r0b = make_float2(xa.z, xa.w);
            float2 r1a = make_float2(xb.x, xb.y), r1b = make_float2(xb.z, xb.w);
            float2 s00 = f2add(b2p[0], r0a);   // row g,   nt=0
            float2 s01 = f2add(b2p[1], r0b);   // row g,   nt=1
            float2 s10 = f2add(b2p[0], r1a);   // row g+8, nt=0
            float2 s11 = f2add(b2p[1], r1b);   // row g+8, nt=1
            C2[0][0] = s00.x; C2[0][1] = s00.y; C2[0][2] = s10.x; C2[0][3] = s10.y;
            C2[1][0] = s01.x; C2[1][1] = s01.y; C2[1][2] = s11.x; C2[1][3] = s11.y;
        }
        #pragma unroll
        for (int nt = 0; nt < 2; nt++)
            #pragma unroll
            for (int kt = 0; kt < 4; kt++)
                mma8(C2[nt][0], C2[nt][1], C2[nt][2], C2[nt][3],
                     bits(ga[kt].x), bits(gb[kt].x), bits(ga[kt].y), bits(gb[kt].y),
                     B2f[kt][nt][0], B2f[kt][nt][1]);

        // ---- store: lane owns out cols 4c..4c+3 of rows g, g+8 -> 2x STG.128 ----
        float* orow = out + (size_t)tile * 16 * DIM;
        *reinterpret_cast<float4*>(orow + g * DIM + 4 * c) =
            make_float4(C2[0][0], C2[0][1], C2[1][0], C2[1][1]);
        *reinterpret_cast<float4*>(orow + (g + 8) * DIM + 4 * c) =
            make_float4(C2[0][2], C2[0][3], C2[1][2], C2[1][3]);
    }
}

extern "C" void kernel_launch(void* const* d_in, const int* in_sizes, int n_in,
                              void* d_out, int out_size)
{
    const float* x    = (const float*)d_in[0];
    const float* ln_w = (const float*)d_in[1];
    const float* ln_b = (const float*)d_in[2];
    const float* w1   = (const float*)d_in[3];
    const float* b1   = (const float*)d_in[4];
    const float* w2   = (const float*)d_in[5];
    const float* b2   = (const float*)d_in[6];
    int nrows  = in_sizes[0] / DIM;
    int ntiles = nrows / 16;
    int tiles_per_cta = WARPS_PER_CTA * TILES_PER_WARP;
    int blocks = (ntiles + tiles_per_cta - 1) / tiles_per_cta;
    fused_ln_mlp_mma<<<blocks, TPB>>>(x, ln_w, ln_b, w1, b1, w2, b2,
                                      (float*)d_out, ntiles);
}

// round 6
// speedup vs baseline: 1.1957x; 1.1957x over previous
#include <cuda_runtime.h>
#include <cstdint>

#define DIM 16
#define HID 32
#define TPB 256
#define WARPS_PER_CTA (TPB / 32)
#define TILES_PER_WARP 8

// ---------------- low-level helpers ----------------
__device__ __forceinline__ unsigned tf32_rna(float f) {   // init-path only
    unsigned u; asm("cvt.rna.tf32.f32 %0, %1;" : "=r"(u) : "f"(f)); return u;
}
__device__ __forceinline__ unsigned bits(float f) { return __float_as_uint(f); }

__device__ __forceinline__ void mma8(float& d0, float& d1, float& d2, float& d3,
                                     unsigned a0, unsigned a1, unsigned a2, unsigned a3,
                                     unsigned b0, unsigned b1) {
    asm volatile(
        "mma.sync.aligned.m16n8k8.row.col.f32.tf32.tf32.f32 "
        "{%0,%1,%2,%3}, {%4,%5,%6,%7}, {%8,%9}, {%0,%1,%2,%3};"
        : "+f"(d0), "+f"(d1), "+f"(d2), "+f"(d3)
        : "r"(a0), "r"(a1), "r"(a2), "r"(a3), "r"(b0), "r"(b1));
}
__device__ __forceinline__ float fast_tanh(float x) {
    float r; asm("tanh.approx.f32 %0, %1;" : "=f"(r) : "f"(x)); return r;
}

union F2U { float2 f; unsigned long long u; };
__device__ __forceinline__ float2 f2fma(float2 a, float2 b, float2 c) {
    F2U A, B, C, R; A.f = a; B.f = b; C.f = c;
    asm("fma.rn.f32x2 %0, %1, %2, %3;" : "=l"(R.u) : "l"(A.u), "l"(B.u), "l"(C.u));
    return R.f;
}
__device__ __forceinline__ float2 f2mul(float2 a, float2 b) {
    F2U A, B, R; A.f = a; B.f = b;
    asm("mul.rn.f32x2 %0, %1, %2;" : "=l"(R.u) : "l"(A.u), "l"(B.u));
    return R.f;
}
__device__ __forceinline__ float2 f2add(float2 a, float2 b) {
    F2U A, B, R; A.f = a; B.f = b;
    asm("add.rn.f32x2 %0, %1, %2;" : "=l"(R.u) : "l"(A.u), "l"(B.u));
    return R.f;
}

// tanh-form GELU on a packed pair
__device__ __forceinline__ float2 gelu2(float2 x) {
    const float C1 = 0.7978845608028654f;            // sqrt(2/pi)
    const float C2 = 0.7978845608028654f * 0.044715f;
    float2 x2 = f2mul(x, x);
    float2 inner = f2fma(x2, make_float2(C2, C2), make_float2(C1, C1));
    float2 y  = f2mul(x, inner);
    float2 t  = make_float2(fast_tanh(y.x), fast_tanh(y.y));
    float2 phi = f2fma(t, make_float2(0.5f, 0.5f), make_float2(0.5f, 0.5f));
    return f2mul(x, phi);
}

// ---------------- fully register-resident tensor-core kernel ----------------
// Same axis-permutation scheme as round 5 (A1 = raw LDG layout, C1 = A2,
// C2 columns = lane's own x columns), plus a depth-2 software pipeline on the
// input tiles so the DRAM latency of tile i+2's load is covered by two full
// iterations of compute.
__global__ void __launch_bounds__(TPB)
fused_ln_mlp_mma(const float* __restrict__ x,
                 const float* __restrict__ ln_w, const float* __restrict__ ln_b,
                 const float* __restrict__ w1,   const float* __restrict__ b1,
                 const float* __restrict__ w2,   const float* __restrict__ b2,
                 float* __restrict__ out, int ntiles)
{
    const int lane = threadIdx.x & 31;
    const int wrp  = threadIdx.x >> 5;
    const int g = lane >> 2;
    const int c = lane & 3;

    // ---- per-warp weight fragments (registers, rna-converted once) ----
    unsigned B1f[2][4][2];
    #pragma unroll
    for (int kt = 0; kt < 2; kt++)
        #pragma unroll
        for (int nt = 0; nt < 4; nt++) {
            B1f[kt][nt][0] = tf32_rna(w1[(nt * 8 + g) * DIM + 4 * c + 2 * kt]);
            B1f[kt][nt][1] = tf32_rna(w1[(nt * 8 + g) * DIM + 4 * c + 2 * kt + 1]);
        }
    unsigned B2f[4][2][2];
    #pragma unroll
    for (int nt = 0; nt < 2; nt++) {
        int od = 4 * (g >> 1) + 2 * nt + (g & 1);
        #pragma unroll
        for (int kt = 0; kt < 4; kt++) {
            B2f[kt][nt][0] = tf32_rna(w2[od * HID + kt * 8 + 2 * c]);
            B2f[kt][nt][1] = tf32_rna(w2[od * HID + kt * 8 + 2 * c + 1]);
        }
    }
    float b1v[4][2];
    #pragma unroll
    for (int nt = 0; nt < 4; nt++) {
        b1v[nt][0] = b1[nt * 8 + 2 * c];
        b1v[nt][1] = b1[nt * 8 + 2 * c + 1];
    }
    float2 b2p[2];
    #pragma unroll
    for (int nt = 0; nt < 2; nt++)
        b2p[nt] = make_float2(b2[4 * c + 2 * nt], b2[4 * c + 2 * nt + 1]);
    const float4 lnw4 = *reinterpret_cast<const float4*>(ln_w + 4 * c);
    const float4 lnb4 = *reinterpret_cast<const float4*>(ln_b + 4 * c);

    const int gwarp = blockIdx.x * WARPS_PER_CTA + wrp;
    const long t0 = (long)gwarp * TILES_PER_WARP;
    if (t0 >= ntiles) return;
    const int n_it = (ntiles - t0 < TILES_PER_WARP) ? (int)(ntiles - t0) : TILES_PER_WARP;

    // ---- depth-2 pipeline: two tiles in flight ----
    float4 bufA[2], bufB[2];
    {
        const float4* p0 = reinterpret_cast<const float4*>(x + (size_t)t0 * 16 * DIM);
        bufA[0] = p0[lane]; bufB[0] = p0[lane + 32];
        if (n_it > 1) {
            const float4* p1 = reinterpret_cast<const float4*>(x + (size_t)(t0 + 1) * 16 * DIM);
            bufA[1] = p1[lane]; bufB[1] = p1[lane + 32];
        }
    }

    #pragma unroll
    for (int it = 0; it < TILES_PER_WARP; ++it) {
        if (it >= n_it) break;
        const long tile = t0 + it;

        const float4 xa = bufA[it & 1], xb = bufB[it & 1];   // rows g / g+8, cols 4c..4c+3
        if (it + 2 < n_it) {
            const float4* p = reinterpret_cast<const float4*>(x + (size_t)(tile + 2) * 16 * DIM);
            bufA[it & 1] = p[lane]; bufB[it & 1] = p[lane + 32];
        }

        float2 xp[4] = { make_float2(xa.x, xb.x), make_float2(xa.y, xb.y),
                         make_float2(xa.z, xb.z), make_float2(xa.w, xb.w) };

        // ---- LayerNorm stats (packed) + quad reduction ----
        float2 s = f2add(f2add(xp[0], xp[1]), f2add(xp[2], xp[3]));
        float2 q = f2mul(xp[0], xp[0]);
        q = f2fma(xp[1], xp[1], q);
        q = f2fma(xp[2], xp[2], q);
        q = f2fma(xp[3], xp[3], q);
        s.x += __shfl_xor_sync(0xffffffffu, s.x, 1); s.x += __shfl_xor_sync(0xffffffffu, s.x, 2);
        s.y += __shfl_xor_sync(0xffffffffu, s.y, 1); s.y += __shfl_xor_sync(0xffffffffu, s.y, 2);
        q.x += __shfl_xor_sync(0xffffffffu, q.x, 1); q.x += __shfl_xor_sync(0xffffffffu, q.x, 2);
        q.y += __shfl_xor_sync(0xffffffffu, q.y, 1); q.y += __shfl_xor_sync(0xffffffffu, q.y, 2);
        const float inv = 1.0f / 16.0f;
        float2 mup = f2mul(s, make_float2(inv, inv));
        float2 qi  = f2mul(q, make_float2(inv, inv));
        float rstd0 = rsqrtf(fmaf(-mup.x, mup.x, qi.x) + 1e-5f);
        float rstd1 = rsqrtf(fmaf(-mup.y, mup.y, qi.y) + 1e-5f);
        float2 rstdp = make_float2(rstd0, rstd1);
        float2 nmup  = make_float2(-mup.x * rstd0, -mup.y * rstd1);

        const float lnw[4] = { lnw4.x, lnw4.y, lnw4.z, lnw4.w };
        const float lnb[4] = { lnb4.x, lnb4.y, lnb4.z, lnb4.w };
        float2 xn[4];
        #pragma unroll
        for (int j = 0; j < 4; j++) {
            float2 wj = make_float2(lnw[j], lnw[j]);
            float2 a = f2mul(rstdp, wj);
            float2 b = f2fma(nmup, wj, make_float2(lnb[j], lnb[j]));
            xn[j] = f2fma(xp[j], a, b);
        }

        // ---- GEMM1 (8 mma), A straight from registers; seeded with b1 ----
        float C1[4][4];
        #pragma unroll
        for (int nt = 0; nt < 4; nt++) {
            C1[nt][0] = b1v[nt][0]; C1[nt][1] = b1v[nt][1];
            C1[nt][2] = b1v[nt][0]; C1[nt][3] = b1v[nt][1];
            mma8(C1[nt][0], C1[nt][1], C1[nt][2], C1[nt][3],
                 bits(xn[0].x), bits(xn[0].y), bits(xn[1].x), bits(xn[1].y),
                 B1f[0][nt][0], B1f[0][nt][1]);
            mma8(C1[nt][0], C1[nt][1], C1[nt][2], C1[nt][3],
                 bits(xn[2].x), bits(xn[2].y), bits(xn[3].x), bits(xn[3].y),
                 B1f[1][nt][0], B1f[1][nt][1]);
        }

        // ---- GELU; C1 fragment IS the GEMM2 A fragment ----
        float2 ga[4], gb[4];
        #pragma unroll
        for (int kt = 0; kt < 4; kt++) {
            ga[kt] = gelu2(make_float2(C1[kt][0], C1[kt][1]));   // row g
            gb[kt] = gelu2(make_float2(C1[kt][2], C1[kt][3]));   // row g+8
        }

        // ---- GEMM2 (8 mma), seeded with b2 + residual from own x registers ----
        float C2[2][4];
        {
            float2 s00 = f2add(b2p[0], make_float2(xa.x, xa.y));
            float2 s01 = f2add(b2p[1], make_float2(xa.z, xa.w));
            float2 s10 = f2add(b2p[0], make_float2(xb.x, xb.y));
            float2 s11 = f2add(b2p[1], make_float2(xb.z, xb.w));
            C2[0][0] = s00.x; C2[0][1] = s00.y; C2[0][2] = s10.x; C2[0][3] = s10.y;
            C2[1][0] = s01.x; C2[1][1] = s01.y; C2[1][2] = s11.x; C2[1][3] = s11.y;
        }
        #pragma unroll
        for (int nt = 0; nt < 2; nt++)
            #pragma unroll
            for (int kt = 0; kt < 4; kt++)
                mma8(C2[nt][0], C2[nt][1], C2[nt][2], C2[nt][3],
                     bits(ga[kt].x), bits(gb[kt].x), bits(ga[kt].y), bits(gb[kt].y),
                     B2f[kt][nt][0], B2f[kt][nt][1]);

        // ---- store: lane owns out cols 4c..4c+3 of rows g, g+8 -> 2x STG.128 ----
        float* orow = out + (size_t)tile * 16 * DIM;
        *reinterpret_cast<float4*>(orow + g * DIM + 4 * c) =
            make_float4(C2[0][0], C2[0][1], C2[1][0], C2[1][1]);
        *reinterpret_cast<float4*>(orow + (g + 8) * DIM + 4 * c) =
            make_float4(C2[0][2], C2[0][3], C2[1][2], C2[1][3]);
    }
}

extern "C" void kernel_launch(void* const* d_in, const int* in_sizes, int n_in,
                              void* d_out, int out_size)
{
    const float* x    = (const float*)d_in[0];
    const float* ln_w = (const float*)d_in[1];
    const float* ln_b = (const float*)d_in[2];
    const float* w1   = (const float*)d_in[3];
    const float* b1   = (const float*)d_in[4];
    const float* w2   = (const float*)d_in[5];
    const float* b2   = (const float*)d_in[6];
    int nrows  = in_sizes[0] / DIM;
    int ntiles = nrows / 16;
    int tiles_per_cta = WARPS_PER_CTA * TILES_PER_WARP;
    int blocks = (ntiles + tiles_per_cta - 1) / tiles_per_cta;
    fused_ln_mlp_mma<<<blocks, TPB>>>(x, ln_w, ln_b, w1, b1, w2, b2,
                                      (float*)d_out, ntiles);
}